// round 2
// baseline (speedup 1.0000x reference)
#include <cuda_runtime.h>

#define H        128
#define NE       400000
#define NN       50000
#define TILE     64
#define THREADS  256

// scatter-add accumulator (scratch; no cudaMalloc allowed)
__device__ float g_agg[NN * H];

__global__ void zero_agg_kernel() {
    int i = blockIdx.x * blockDim.x + threadIdx.x;
    if (i < NN * H) g_agg[i] = 0.0f;
}

// ---------------------------------------------------------------------------
// Tile GEMM: acc[8][4] += sAct[e0+e][k] * W[k][c0+c]
// Weights streamed through smem in KCHUNK slabs. LDA/KCHUNK compile-time.
// Warp layout: warp w owns rows e0=w*8..w*8+7 (activation loads broadcast),
// lane l owns cols c0=l*4..l*4+3 (weight loads conflict-free float4).
// ---------------------------------------------------------------------------
template<int LDA, int KCHUNK, int NCHUNK>
__device__ __forceinline__ void gemm_tile(const float* __restrict__ W,
                                          const float* sAct, float* sW,
                                          float acc[8][4], int e0, int c0)
{
    #pragma unroll 1
    for (int cb = 0; cb < NCHUNK; ++cb) {
        __syncthreads();  // prev users of sW / sAct-writers done
        const float4* gw  = (const float4*)(W + (size_t)cb * KCHUNK * H);
        float4*       sw4 = (float4*)sW;
        constexpr int NLD = (KCHUNK * H / 4) / THREADS;
        #pragma unroll
        for (int i = 0; i < NLD; ++i)
            sw4[threadIdx.x + i * THREADS] = gw[threadIdx.x + i * THREADS];
        __syncthreads();

        const float* aptr = sAct + e0 * LDA + cb * KCHUNK;
        #pragma unroll 4
        for (int k = 0; k < KCHUNK; ++k) {
            float4 w = *(const float4*)(sW + k * H + c0);
            #pragma unroll
            for (int e = 0; e < 8; ++e) {
                float a = aptr[e * LDA + k];
                acc[e][0] = fmaf(a, w.x, acc[e][0]);
                acc[e][1] = fmaf(a, w.y, acc[e][1]);
                acc[e][2] = fmaf(a, w.z, acc[e][2]);
                acc[e][3] = fmaf(a, w.w, acc[e][3]);
            }
        }
    }
    __syncthreads();  // all reads of sAct done before caller overwrites it
}

__device__ __forceinline__ void zero_acc(float acc[8][4]) {
    #pragma unroll
    for (int e = 0; e < 8; ++e)
        #pragma unroll
        for (int c = 0; c < 4; ++c) acc[e][c] = 0.0f;
}

// bias + ReLU + LayerNorm (over H=128, all cols of a row live in one warp),
// result written back to sAct as a [TILE][H] tile (ld = H).
__device__ __forceinline__ void relu_ln_store(float acc[8][4],
        const float* __restrict__ b, const float* __restrict__ g,
        const float* __restrict__ bt, float* sOut, int e0, int c0)
{
    float bb[4], gg[4], tt[4];
    #pragma unroll
    for (int c = 0; c < 4; ++c) { bb[c] = b[c0+c]; gg[c] = g[c0+c]; tt[c] = bt[c0+c]; }
    #pragma unroll
    for (int e = 0; e < 8; ++e) {
        float v[4]; float s = 0.0f, s2 = 0.0f;
        #pragma unroll
        for (int c = 0; c < 4; ++c) {
            float t = fmaxf(acc[e][c] + bb[c], 0.0f);
            v[c] = t; s += t; s2 = fmaf(t, t, s2);
        }
        #pragma unroll
        for (int off = 16; off > 0; off >>= 1) {
            s  += __shfl_xor_sync(0xffffffffu, s,  off);
            s2 += __shfl_xor_sync(0xffffffffu, s2, off);
        }
        float mean = s * (1.0f / H);
        float var  = fmaf(-mean, mean, s2 * (1.0f / H));
        float inv  = rsqrtf(var + 1e-5f);
        #pragma unroll
        for (int c = 0; c < 4; ++c)
            sOut[(e0 + e) * H + c0 + c] = (v[c] - mean) * inv * gg[c] + tt[c];
    }
}

// ---------------------------------------------------------------------------
// Edge block: gather [edge_attr | x[src] | x[dst]] -> 4-layer MLP ->
//   out_edge = edge_attr + mlp ; atomic scatter-add mlp (pre-residual) to agg
// smem: 64*384 act + 192*128 W = 196608 B dynamic
// ---------------------------------------------------------------------------
__global__ void __launch_bounds__(THREADS, 1) edge_kernel(
    const float* __restrict__ x, const float* __restrict__ edge_attr,
    const int* __restrict__ edge_index,   // int32, [2][NE]
    const float* __restrict__ W1, const float* __restrict__ b1,
    const float* __restrict__ W2, const float* __restrict__ b2,
    const float* __restrict__ W3, const float* __restrict__ b3,
    const float* __restrict__ W4, const float* __restrict__ b4,
    const float* __restrict__ g1, const float* __restrict__ t1,
    const float* __restrict__ g2, const float* __restrict__ t2,
    const float* __restrict__ g3, const float* __restrict__ t3,
    float* __restrict__ out_edge)
{
    extern __shared__ float smem[];
    float* sAct = smem;               // [64][384]
    float* sW   = smem + TILE * 384;  // [192][128]
    __shared__ int sSrc[TILE];
    __shared__ int sDst[TILE];

    int tid = threadIdx.x;
    long long ebase = (long long)blockIdx.x * TILE;

    if (tid < TILE) {
        sSrc[tid] = edge_index[ebase + tid];
        sDst[tid] = edge_index[NE + ebase + tid];
    }
    __syncthreads();

    // gather (float4, coalesced along feature dim)
    for (int i = tid; i < TILE * 96; i += THREADS) {  // 384/4 = 96 float4/row
        int e  = i / 96;
        int f4 = i % 96;
        long long edge = ebase + e;
        float4 val;
        if (f4 < 32)      val = ((const float4*)(edge_attr + edge * H))[f4];
        else if (f4 < 64) val = ((const float4*)(x + (long long)sSrc[e] * H))[f4 - 32];
        else              val = ((const float4*)(x + (long long)sDst[e] * H))[f4 - 64];
        ((float4*)(sAct + e * 384))[f4] = val;
    }
    // (gemm_tile's leading __syncthreads covers gather completion)

    int e0 = (tid >> 5) * 8;
    int c0 = (tid & 31) * 4;
    float acc[8][4];

    zero_acc(acc);
    gemm_tile<384, 192, 2>(W1, sAct, sW, acc, e0, c0);
    relu_ln_store(acc, b1, g1, t1, sAct, e0, c0);

    zero_acc(acc);
    gemm_tile<128, 128, 1>(W2, sAct, sW, acc, e0, c0);
    relu_ln_store(acc, b2, g2, t2, sAct, e0, c0);

    zero_acc(acc);
    gemm_tile<128, 128, 1>(W3, sAct, sW, acc, e0, c0);
    relu_ln_store(acc, b3, g3, t3, sAct, e0, c0);

    zero_acc(acc);
    gemm_tile<128, 128, 1>(W4, sAct, sW, acc, e0, c0);

    // epilogue: residual write + scatter-add of pre-residual edge_new
    #pragma unroll
    for (int e = 0; e < 8; ++e) {
        long long edge = ebase + e0 + e;
        const float* ea = edge_attr + edge * H + c0;
        float*       oe = out_edge  + edge * H + c0;
        float*       ag = g_agg + (long long)sDst[e0 + e] * H + c0;
        #pragma unroll
        for (int c = 0; c < 4; ++c) {
            float val = acc[e][c] + b4[c0 + c];
            oe[c] = ea[c] + val;
            atomicAdd(ag + c, val);
        }
    }
}

// ---------------------------------------------------------------------------
// Node block: concat [x | agg] -> 4-layer MLP -> out_node = x + mlp
// smem: 64*256 act + 256*128 W = 196608 B dynamic
// ---------------------------------------------------------------------------
__global__ void __launch_bounds__(THREADS, 1) node_kernel(
    const float* __restrict__ x,
    const float* __restrict__ W1, const float* __restrict__ b1,
    const float* __restrict__ W2, const float* __restrict__ b2,
    const float* __restrict__ W3, const float* __restrict__ b3,
    const float* __restrict__ W4, const float* __restrict__ b4,
    const float* __restrict__ g1, const float* __restrict__ t1,
    const float* __restrict__ g2, const float* __restrict__ t2,
    const float* __restrict__ g3, const float* __restrict__ t3,
    float* __restrict__ out_node)
{
    extern __shared__ float smem[];
    float* sAct = smem;               // [64][256]
    float* sW   = smem + TILE * 256;  // [256][128]

    int tid = threadIdx.x;
    long long nbase = (long long)blockIdx.x * TILE;

    for (int i = tid; i < TILE * 64; i += THREADS) {  // 256/4 = 64 float4/row
        int e  = i / 64;
        int f4 = i % 64;
        long long node = nbase + e;
        float4 val = make_float4(0.f, 0.f, 0.f, 0.f);
        if (node < NN) {
            if (f4 < 32) val = ((const float4*)(x     + node * H))[f4];
            else         val = ((const float4*)(g_agg + node * H))[f4 - 32];
        }
        ((float4*)(sAct + e * 256))[f4] = val;
    }

    int e0 = (tid >> 5) * 8;
    int c0 = (tid & 31) * 4;
    float acc[8][4];

    zero_acc(acc);
    gemm_tile<256, 256, 1>(W1, sAct, sW, acc, e0, c0);
    relu_ln_store(acc, b1, g1, t1, sAct, e0, c0);

    zero_acc(acc);
    gemm_tile<128, 128, 1>(W2, sAct, sW, acc, e0, c0);
    relu_ln_store(acc, b2, g2, t2, sAct, e0, c0);

    zero_acc(acc);
    gemm_tile<128, 128, 1>(W3, sAct, sW, acc, e0, c0);
    relu_ln_store(acc, b3, g3, t3, sAct, e0, c0);

    zero_acc(acc);
    gemm_tile<128, 128, 1>(W4, sAct, sW, acc, e0, c0);

    #pragma unroll
    for (int e = 0; e < 8; ++e) {
        long long node = nbase + e0 + e;
        if (node < NN) {
            const float* xr = x        + node * H + c0;
            float*       on = out_node + node * H + c0;
            #pragma unroll
            for (int c = 0; c < 4; ++c)
                on[c] = xr[c] + acc[e][c] + b4[c0 + c];
        }
    }
}

extern "C" void kernel_launch(void* const* d_in, const int* in_sizes, int n_in,
                              void* d_out, int out_size)
{
    const float* x          = (const float*)d_in[0];
    const float* edge_attr  = (const float*)d_in[1];
    const int*   edge_index = (const int*)d_in[2];   // int32 (JAX x64 disabled)

    const float* eW1 = (const float*)d_in[3];  const float* eb1 = (const float*)d_in[4];
    const float* eW2 = (const float*)d_in[5];  const float* eb2 = (const float*)d_in[6];
    const float* eW3 = (const float*)d_in[7];  const float* eb3 = (const float*)d_in[8];
    const float* eW4 = (const float*)d_in[9];  const float* eb4 = (const float*)d_in[10];
    const float* eg1 = (const float*)d_in[11]; const float* et1 = (const float*)d_in[12];
    const float* eg2 = (const float*)d_in[13]; const float* et2 = (const float*)d_in[14];
    const float* eg3 = (const float*)d_in[15]; const float* et3 = (const float*)d_in[16];

    const float* nW1 = (const float*)d_in[17]; const float* nb1 = (const float*)d_in[18];
    const float* nW2 = (const float*)d_in[19]; const float* nb2 = (const float*)d_in[20];
    const float* nW3 = (const float*)d_in[21]; const float* nb3 = (const float*)d_in[22];
    const float* nW4 = (const float*)d_in[23]; const float* nb4 = (const float*)d_in[24];
    const float* ng1 = (const float*)d_in[25]; const float* nt1 = (const float*)d_in[26];
    const float* ng2 = (const float*)d_in[27]; const float* nt2 = (const float*)d_in[28];
    const float* ng3 = (const float*)d_in[29]; const float* nt3 = (const float*)d_in[30];

    float* out_node = (float*)d_out;                     // [NN*H]
    float* out_edge = (float*)d_out + (size_t)NN * H;    // [NE*H]

    const int SMEM = 196608;
    cudaFuncSetAttribute(edge_kernel, cudaFuncAttributeMaxDynamicSharedMemorySize, SMEM);
    cudaFuncSetAttribute(node_kernel, cudaFuncAttributeMaxDynamicSharedMemorySize, SMEM);

    zero_agg_kernel<<<(NN * H + 1023) / 1024, 1024>>>();

    edge_kernel<<<NE / TILE, THREADS, SMEM>>>(
        x, edge_attr, edge_index,
        eW1, eb1, eW2, eb2, eW3, eb3, eW4, eb4,
        eg1, et1, eg2, et2, eg3, et3,
        out_edge);

    node_kernel<<<(NN + TILE - 1) / TILE, THREADS, SMEM>>>(
        x,
        nW1, nb1, nW2, nb2, nW3, nb3, nW4, nb4,
        ng1, nt1, ng2, nt2, ng3, nt3,
        out_node);
}

// round 5
// speedup vs baseline: 1.4473x; 1.4473x over previous
#include <cuda_runtime.h>
#include <cstdint>

#define H        128
#define NE       400000
#define NN       50000
#define THREADS  256
#define SA_STR   132   // floats; A rows conflict-free
#define SB_STR   136   // floats; B rows conflict-free

// scratch (no cudaMalloc allowed)
__device__ float g_agg[NN * H];

__global__ void zero_agg_kernel() {
    int i = blockIdx.x * blockDim.x + threadIdx.x;
    if (i < NN * H) g_agg[i] = 0.0f;
}

// ---------------------------------------------------------------- helpers
__device__ __forceinline__ uint32_t tf32r(float x) {
    uint32_t o; asm("cvt.rna.tf32.f32 %0, %1;" : "=r"(o) : "f"(x));
    return o;
}
__device__ __forceinline__ uint32_t tf32lo(float x, uint32_t hi) {
    return tf32r(x - __uint_as_float(hi));
}

__device__ __forceinline__ void mma_tf32(float d[4], uint32_t a0, uint32_t a1,
                                         uint32_t a2, uint32_t a3,
                                         uint32_t b0, uint32_t b1) {
    asm volatile(
        "mma.sync.aligned.m16n8k8.row.col.f32.tf32.tf32.f32 "
        "{%0,%1,%2,%3}, {%4,%5,%6,%7}, {%8,%9}, {%0,%1,%2,%3};"
        : "+f"(d[0]), "+f"(d[1]), "+f"(d[2]), "+f"(d[3])
        : "r"(a0), "r"(a1), "r"(a2), "r"(a3), "r"(b0), "r"(b1));
}

// Warp w computes rows [w*16, w*16+16) x all 128 cols, split-tf32 (3 MMA/tile).
__device__ __forceinline__ void gemm128(const float* sA, const uint32_t* sBh,
                                        const uint32_t* sBl, float acc[16][4]) {
    int lane = threadIdx.x & 31;
    int gid  = lane >> 2, tig = lane & 3;
    const float* Ar0 = sA + ((threadIdx.x >> 5) * 16 + gid) * SA_STR;
    const float* Ar8 = Ar0 + 8 * SA_STR;
    #pragma unroll 1
    for (int ks = 0; ks < 16; ++ks) {
        int k0 = ks * 8;
        float a0f = Ar0[k0 + tig],     a1f = Ar8[k0 + tig];
        float a2f = Ar0[k0 + tig + 4], a3f = Ar8[k0 + tig + 4];
        uint32_t a0h = tf32r(a0f), a1h = tf32r(a1f), a2h = tf32r(a2f), a3h = tf32r(a3f);
        uint32_t a0l = tf32lo(a0f, a0h), a1l = tf32lo(a1f, a1h);
        uint32_t a2l = tf32lo(a2f, a2h), a3l = tf32lo(a3f, a3h);
        const uint32_t* B0h = sBh + (k0 + tig) * SB_STR + gid;
        const uint32_t* B1h = B0h + 4 * SB_STR;
        const uint32_t* B0l = sBl + (k0 + tig) * SB_STR + gid;
        const uint32_t* B1l = B0l + 4 * SB_STR;
        #pragma unroll
        for (int nt = 0; nt < 16; ++nt) {
            uint32_t bh0 = B0h[nt * 8], bh1 = B1h[nt * 8];
            uint32_t bl0 = B0l[nt * 8], bl1 = B1l[nt * 8];
            mma_tf32(acc[nt], a0h, a1h, a2h, a3h, bh0, bh1);
            mma_tf32(acc[nt], a0l, a1l, a2l, a3l, bh0, bh1);
            mma_tf32(acc[nt], a0h, a1h, a2h, a3h, bl0, bl1);
        }
    }
}

// Split one 128x128 weight chunk (row-major [k][n]) into sBh/sBl
__device__ __forceinline__ void fill_B(uint32_t* sBh, uint32_t* sBl,
                                       const float* __restrict__ W) {
    #pragma unroll
    for (int i = threadIdx.x; i < 4096; i += THREADS) {
        int k = i >> 5, j = i & 31;
        float4 v = ((const float4*)(W + (size_t)k * H))[j];
        uint4 uh = make_uint4(tf32r(v.x), tf32r(v.y), tf32r(v.z), tf32r(v.w));
        uint4 ul = make_uint4(tf32lo(v.x, uh.x), tf32lo(v.y, uh.y),
                              tf32lo(v.z, uh.z), tf32lo(v.w, uh.w));
        *(uint4*)(sBh + k * SB_STR + j * 4) = uh;
        *(uint4*)(sBl + k * SB_STR + j * 4) = ul;
    }
}

// bias + ReLU + LayerNorm fully in registers; write f32 next-layer A into sA
__device__ __forceinline__ void epi_ln(float acc[16][4], const float* sPar, int l,
                                       float* sA) {
    int lane = threadIdx.x & 31;
    int gid  = lane >> 2, tig = lane & 3;
    const float* bb = sPar + l * 3 * 128;
    const float* gg = bb + 128;
    const float* tt = bb + 256;
    float sa = 0.f, sa2 = 0.f, sb = 0.f, sb2 = 0.f;
    #pragma unroll
    for (int nt = 0; nt < 16; ++nt) {
        int col = nt * 8 + 2 * tig;
        float2 b = *(const float2*)(bb + col);
        float t0 = fmaxf(acc[nt][0] + b.x, 0.f);
        float t1 = fmaxf(acc[nt][1] + b.y, 0.f);
        float t2 = fmaxf(acc[nt][2] + b.x, 0.f);
        float t3 = fmaxf(acc[nt][3] + b.y, 0.f);
        acc[nt][0] = t0; acc[nt][1] = t1; acc[nt][2] = t2; acc[nt][3] = t3;
        sa += t0 + t1; sa2 = fmaf(t0, t0, fmaf(t1, t1, sa2));
        sb += t2 + t3; sb2 = fmaf(t2, t2, fmaf(t3, t3, sb2));
    }
    #pragma unroll
    for (int m = 1; m <= 2; m <<= 1) {
        sa  += __shfl_xor_sync(0xffffffffu, sa,  m);
        sa2 += __shfl_xor_sync(0xffffffffu, sa2, m);
        sb  += __shfl_xor_sync(0xffffffffu, sb,  m);
        sb2 += __shfl_xor_sync(0xffffffffu, sb2, m);
    }
    float ma = sa * 0.0078125f, mb = sb * 0.0078125f;
    float ia = rsqrtf(fmaf(-ma, ma, sa2 * 0.0078125f) + 1e-5f);
    float ib = rsqrtf(fmaf(-mb, mb, sb2 * 0.0078125f) + 1e-5f);
    int ra = (threadIdx.x >> 5) * 16 + gid;
    #pragma unroll
    for (int nt = 0; nt < 16; ++nt) {
        int col = nt * 8 + 2 * tig;
        float2 g = *(const float2*)(gg + col);
        float2 t = *(const float2*)(tt + col);
        float2 va, vb;
        va.x = fmaf((acc[nt][0] - ma) * ia, g.x, t.x);
        va.y = fmaf((acc[nt][1] - ma) * ia, g.y, t.y);
        vb.x = fmaf((acc[nt][2] - mb) * ib, g.x, t.x);
        vb.y = fmaf((acc[nt][3] - mb) * ib, g.y, t.y);
        *(float2*)(sA + ra * SA_STR + col)       = va;
        *(float2*)(sA + (ra + 8) * SA_STR + col) = vb;
    }
}

// final layer: acc + b4 -> sC (f32, stride SA_STR; aliases sA)
__device__ __forceinline__ void epi_final(float acc[16][4], const float* sPar,
                                          float* sC) {
    int lane = threadIdx.x & 31;
    int gid  = lane >> 2, tig = lane & 3;
    const float* b4 = sPar + 9 * 128;
    int ra = (threadIdx.x >> 5) * 16 + gid;
    #pragma unroll
    for (int nt = 0; nt < 16; ++nt) {
        int col = nt * 8 + 2 * tig;
        float2 b = *(const float2*)(b4 + col);
        float2 va, vb;
        va.x = acc[nt][0] + b.x; va.y = acc[nt][1] + b.y;
        vb.x = acc[nt][2] + b.x; vb.y = acc[nt][3] + b.y;
        *(float2*)(sC + ra * SA_STR + col)       = va;
        *(float2*)(sC + (ra + 8) * SA_STR + col) = vb;
    }
}

__device__ __forceinline__ void zero_acc(float acc[16][4]) {
    #pragma unroll
    for (int nt = 0; nt < 16; ++nt)
        #pragma unroll
        for (int c = 0; c < 4; ++c) acc[nt][c] = 0.0f;
}

// ---------------------------------------------------------------- edge kernel
__global__ void __launch_bounds__(THREADS)
edge_kernel(const float* __restrict__ x, const float* __restrict__ edge_attr,
            const int* __restrict__ edge_index,
            const float* __restrict__ W1, const float* __restrict__ W2,
            const float* __restrict__ W3, const float* __restrict__ W4,
            const float* __restrict__ b1, const float* __restrict__ g1, const float* __restrict__ t1,
            const float* __restrict__ b2, const float* __restrict__ g2, const float* __restrict__ t2,
            const float* __restrict__ b3, const float* __restrict__ g3, const float* __restrict__ t3,
            const float* __restrict__ b4,
            float* __restrict__ out_edge)
{
    extern __shared__ float smem[];
    float*    sA  = smem;                                   // [128][SA_STR] f32
    uint32_t* sBh = (uint32_t*)(smem + 128 * SA_STR);       // [128][SB_STR] tf32 hi
    uint32_t* sBl = sBh + 128 * SB_STR;                     // [128][SB_STR] tf32 lo
    __shared__ float sPar[10 * 128];
    __shared__ int   sSrc[128], sDst[128];

    int tid = threadIdx.x;
    size_t ebase = (size_t)blockIdx.x * 128;

    if (tid < 128) {
        sPar[0*128+tid] = b1[tid]; sPar[1*128+tid] = g1[tid]; sPar[2*128+tid] = t1[tid];
        sPar[3*128+tid] = b2[tid]; sPar[4*128+tid] = g2[tid]; sPar[5*128+tid] = t2[tid];
        sPar[6*128+tid] = b3[tid]; sPar[7*128+tid] = g3[tid]; sPar[8*128+tid] = t3[tid];
        sPar[9*128+tid] = b4[tid];
        sSrc[tid] = edge_index[ebase + tid];
        sDst[tid] = edge_index[(size_t)NE + ebase + tid];
    }
    __syncthreads();

    float acc[16][4];
    zero_acc(acc);

    // ---- layer 1: K = 384 in 3 chunks, accumulate in registers
    #pragma unroll 1
    for (int c = 0; c < 3; ++c) {
        #pragma unroll
        for (int i = tid; i < 4096; i += THREADS) {
            int r = i >> 5, j = i & 31;
            const float* src = (c == 0) ? edge_attr + (ebase + r) * H
                                        : x + (size_t)(c == 1 ? sSrc[r] : sDst[r]) * H;
            float4 v = ((const float4*)src)[j];
            *(float4*)(sA + r * SA_STR + j * 4) = v;
        }
        fill_B(sBh, sBl, W1 + (size_t)c * 128 * H);
        __syncthreads();
        gemm128(sA, sBh, sBl, acc);
        __syncthreads();
    }

    // ---- layers 2..4
    const float* Ws[3] = {W2, W3, W4};
    #pragma unroll 1
    for (int l = 0; l < 3; ++l) {
        epi_ln(acc, sPar, l, sA);
        fill_B(sBh, sBl, Ws[l]);
        __syncthreads();
        zero_acc(acc);
        gemm128(sA, sBh, sBl, acc);
        __syncthreads();
    }

    // ---- final: + b4, residual write, atomic scatter of pre-residual
    epi_final(acc, sPar, sA);
    __syncthreads();

    #pragma unroll
    for (int i = tid; i < 4096; i += THREADS) {
        int r = i >> 5, j = i & 31;
        float4 val = *(float4*)(sA + r * SA_STR + j * 4);
        size_t e = ebase + r;
        float4 ea = ((const float4*)(edge_attr + e * H))[j];
        float4 o;
        o.x = ea.x + val.x; o.y = ea.y + val.y; o.z = ea.z + val.z; o.w = ea.w + val.w;
        ((float4*)(out_edge + e * H))[j] = o;
        atomicAdd((float4*)(g_agg + (size_t)sDst[r] * H + j * 4), val);
    }
}

// ---------------------------------------------------------------- node kernel
__global__ void __launch_bounds__(THREADS)
node_kernel(const float* __restrict__ x,
            const float* __restrict__ W1, const float* __restrict__ W2,
            const float* __restrict__ W3, const float* __restrict__ W4,
            const float* __restrict__ b1, const float* __restrict__ g1, const float* __restrict__ t1,
            const float* __restrict__ b2, const float* __restrict__ g2, const float* __restrict__ t2,
            const float* __restrict__ b3, const float* __restrict__ g3, const float* __restrict__ t3,
            const float* __restrict__ b4,
            float* __restrict__ out_node)
{
    extern __shared__ float smem[];
    float*    sA  = smem;
    uint32_t* sBh = (uint32_t*)(smem + 128 * SA_STR);
    uint32_t* sBl = sBh + 128 * SB_STR;
    __shared__ float sPar[10 * 128];

    int tid = threadIdx.x;
    size_t nbase = (size_t)blockIdx.x * 128;

    if (tid < 128) {
        sPar[0*128+tid] = b1[tid]; sPar[1*128+tid] = g1[tid]; sPar[2*128+tid] = t1[tid];
        sPar[3*128+tid] = b2[tid]; sPar[4*128+tid] = g2[tid]; sPar[5*128+tid] = t2[tid];
        sPar[6*128+tid] = b3[tid]; sPar[7*128+tid] = g3[tid]; sPar[8*128+tid] = t3[tid];
        sPar[9*128+tid] = b4[tid];
    }
    __syncthreads();

    float acc[16][4];
    zero_acc(acc);

    // ---- layer 1: K = 256 in 2 chunks ([x | agg])
    #pragma unroll 1
    for (int c = 0; c < 2; ++c) {
        const float* src0 = (c == 0) ? x : g_agg;
        #pragma unroll
        for (int i = tid; i < 4096; i += THREADS) {
            int r = i >> 5, j = i & 31;
            size_t node = nbase + r;
            float4 v = make_float4(0.f, 0.f, 0.f, 0.f);
            if (node < NN) v = ((const float4*)(src0 + node * H))[j];
            *(float4*)(sA + r * SA_STR + j * 4) = v;
        }
        fill_B(sBh, sBl, W1 + (size_t)c * 128 * H);
        __syncthreads();
        gemm128(sA, sBh, sBl, acc);
        __syncthreads();
    }

    const float* Ws[3] = {W2, W3, W4};
    #pragma unroll 1
    for (int l = 0; l < 3; ++l) {
        epi_ln(acc, sPar, l, sA);
        fill_B(sBh, sBl, Ws[l]);
        __syncthreads();
        zero_acc(acc);
        gemm128(sA, sBh, sBl, acc);
        __syncthreads();
    }

    epi_final(acc, sPar, sA);
    __syncthreads();

    #pragma unroll
    for (int i = tid; i < 4096; i += THREADS) {
        int r = i >> 5, j = i & 31;
        size_t node = nbase + r;
        if (node < NN) {
            float4 val = *(float4*)(sA + r * SA_STR + j * 4);
            float4 xv = ((const float4*)(x + node * H))[j];
            float4 o;
            o.x = xv.x + val.x; o.y = xv.y + val.y; o.z = xv.z + val.z; o.w = xv.w + val.w;
            ((float4*)(out_node + node * H))[j] = o;
        }
    }
}

// ---------------------------------------------------------------- launch
extern "C" void kernel_launch(void* const* d_in, const int* in_sizes, int n_in,
                              void* d_out, int out_size)
{
    const float* x          = (const float*)d_in[0];
    const float* edge_attr  = (const float*)d_in[1];
    const int*   edge_index = (const int*)d_in[2];

    const float* eW1 = (const float*)d_in[3];  const float* eb1 = (const float*)d_in[4];
    const float* eW2 = (const float*)d_in[5];  const float* eb2 = (const float*)d_in[6];
    const float* eW3 = (const float*)d_in[7];  const float* eb3 = (const float*)d_in[8];
    const float* eW4 = (const float*)d_in[9];  const float* eb4 = (const float*)d_in[10];
    const float* eg1 = (const float*)d_in[11]; const float* et1 = (const float*)d_in[12];
    const float* eg2 = (const float*)d_in[13]; const float* et2 = (const float*)d_in[14];
    const float* eg3 = (const float*)d_in[15]; const float* et3 = (const float*)d_in[16];

    const float* nW1 = (const float*)d_in[17]; const float* nb1 = (const float*)d_in[18];
    const float* nW2 = (const float*)d_in[19]; const float* nb2 = (const float*)d_in[20];
    const float* nW3 = (const float*)d_in[21]; const float* nb3 = (const float*)d_in[22];
    const float* nW4 = (const float*)d_in[23]; const float* nb4 = (const float*)d_in[24];
    const float* ng1 = (const float*)d_in[25]; const float* nt1 = (const float*)d_in[26];
    const float* ng2 = (const float*)d_in[27]; const float* nt2 = (const float*)d_in[28];
    const float* ng3 = (const float*)d_in[29]; const float* nt3 = (const float*)d_in[30];

    float* out_node = (float*)d_out;                   // [NN*H]
    float* out_edge = (float*)d_out + (size_t)NN * H;  // [NE*H]

    const int SMEM = (128 * SA_STR + 2 * 128 * SB_STR) * 4;  // 206848 B
    cudaFuncSetAttribute(edge_kernel, cudaFuncAttributeMaxDynamicSharedMemorySize, SMEM);
    cudaFuncSetAttribute(node_kernel, cudaFuncAttributeMaxDynamicSharedMemorySize, SMEM);

    zero_agg_kernel<<<(NN * H + 1023) / 1024, 1024>>>();

    edge_kernel<<<NE / 128, THREADS, SMEM>>>(
        x, edge_attr, edge_index,
        eW1, eW2, eW3, eW4,
        eb1, eg1, et1, eb2, eg2, et2, eb3, eg3, et3, eb4,
        out_edge);

    node_kernel<<<(NN + 127) / 128, THREADS, SMEM>>>(
        x,
        nW1, nW2, nW3, nW4,
        nb1, ng1, nt1, nb2, ng2, nt2, nb3, ng3, nt3, nb4,
        out_node);
}

// round 6
// speedup vs baseline: 2.1264x; 1.4692x over previous
#include <cuda_runtime.h>
#include <cuda_bf16.h>
#include <cstdint>

#define H        128
#define NE       400000
#define NN       50000
#define THREADS  256
#define SA_STR   136   // floats; stride%32==8 -> conflict-free float2 frag loads
#define SBW      136   // u32;    stride%32==8 -> conflict-free b frag loads

// scratch (no cudaMalloc allowed)
__device__ float g_agg[NN * H];

__global__ void zero_agg_kernel() {
    int i = blockIdx.x * blockDim.x + threadIdx.x;
    if (i < NN * H) g_agg[i] = 0.0f;
}

// ---------------------------------------------------------------- helpers
__device__ __forceinline__ void split2(float2 v, uint32_t& hi, uint32_t& lo) {
    __nv_bfloat162 h = __float22bfloat162_rn(v);
    float2 hf = __bfloat1622float2(h);
    __nv_bfloat162 l = __float22bfloat162_rn(make_float2(v.x - hf.x, v.y - hf.y));
    hi = *(uint32_t*)&h;
    lo = *(uint32_t*)&l;
}

__device__ __forceinline__ void mma_bf16(float d[4], const uint32_t a[4],
                                         uint32_t b0, uint32_t b1) {
    asm volatile(
        "mma.sync.aligned.m16n8k16.row.col.f32.bf16.bf16.f32 "
        "{%0,%1,%2,%3}, {%4,%5,%6,%7}, {%8,%9}, {%0,%1,%2,%3};"
        : "+f"(d[0]), "+f"(d[1]), "+f"(d[2]), "+f"(d[3])
        : "r"(a[0]), "r"(a[1]), "r"(a[2]), "r"(a[3]), "r"(b0), "r"(b1));
}

// Warp tile m32 x n64: wm = w>>1 (rows 32*wm..+31), nb = w&1 (cols 64*nb..+63).
// acc[mb][nt][4]: mb in {0,1} row blocks of 16, nt in 0..7 col tiles of 8.
// Split-bf16: acc += A_hi*B_hi + A_lo*B_hi + A_hi*B_lo.
__device__ __forceinline__ void gemm128(const float* sA, const uint32_t* sBh,
                                        const uint32_t* sBl, float acc[2][8][4],
                                        int rb, int nb) {
    int lane = threadIdx.x & 31;
    int gid  = lane >> 2, tig = lane & 3;
    const float* A0 = sA + (rb + gid) * SA_STR;
    int bcol = nb * 64 + gid;
    #pragma unroll 1
    for (int ks = 0; ks < 8; ++ks) {
        int k0 = ks * 16;
        uint32_t ah[2][4], al[2][4];
        #pragma unroll
        for (int mb = 0; mb < 2; ++mb) {
            const float* Ar0 = A0 + (mb * 16) * SA_STR + k0 + 2 * tig;
            const float* Ar8 = Ar0 + 8 * SA_STR;
            split2(*(const float2*)(Ar0),     ah[mb][0], al[mb][0]);
            split2(*(const float2*)(Ar8),     ah[mb][1], al[mb][1]);
            split2(*(const float2*)(Ar0 + 8), ah[mb][2], al[mb][2]);
            split2(*(const float2*)(Ar8 + 8), ah[mb][3], al[mb][3]);
        }
        const uint32_t* Bh0 = sBh + (ks * 8 + tig) * SBW + bcol;
        const uint32_t* Bh1 = Bh0 + 4 * SBW;
        const uint32_t* Bl0 = sBl + (ks * 8 + tig) * SBW + bcol;
        const uint32_t* Bl1 = Bl0 + 4 * SBW;
        #pragma unroll
        for (int nt = 0; nt < 8; ++nt) {
            uint32_t bh0 = Bh0[nt * 8], bh1 = Bh1[nt * 8];
            uint32_t bl0 = Bl0[nt * 8], bl1 = Bl1[nt * 8];
            #pragma unroll
            for (int mb = 0; mb < 2; ++mb) {
                mma_bf16(acc[mb][nt], ah[mb], bh0, bh1);
                mma_bf16(acc[mb][nt], al[mb], bh0, bh1);
                mma_bf16(acc[mb][nt], ah[mb], bl0, bl1);
            }
        }
    }
}

// Pack one 128x128 weight chunk (row-major [k][n]) into k-paired bf16x2 hi/lo
__device__ __forceinline__ void fill_B(uint32_t* sBh, uint32_t* sBl,
                                       const float* __restrict__ W) {
    #pragma unroll
    for (int i = threadIdx.x; i < 2048; i += THREADS) {
        int kp = i >> 5, j = i & 31;                 // kp: k-pair, j: float4 group
        float4 v0 = ((const float4*)(W + (size_t)(2 * kp)     * H))[j];
        float4 v1 = ((const float4*)(W + (size_t)(2 * kp + 1) * H))[j];
        uint4 uh, ul;
        split2(make_float2(v0.x, v1.x), uh.x, ul.x);
        split2(make_float2(v0.y, v1.y), uh.y, ul.y);
        split2(make_float2(v0.z, v1.z), uh.z, ul.z);
        split2(make_float2(v0.w, v1.w), uh.w, ul.w);
        *(uint4*)(sBh + kp * SBW + j * 4) = uh;
        *(uint4*)(sBl + kp * SBW + j * 4) = ul;
    }
}

__device__ __forceinline__ void zero_acc(float acc[2][8][4]) {
    #pragma unroll
    for (int mb = 0; mb < 2; ++mb)
        #pragma unroll
        for (int nt = 0; nt < 8; ++nt)
            #pragma unroll
            for (int c = 0; c < 4; ++c) acc[mb][nt][c] = 0.0f;
}

// bias + ReLU + LayerNorm (two-phase; rows split across 2 n-warps); f32 out to sA
__device__ __forceinline__ void epi_ln(float acc[2][8][4], const float* sPar, int l,
                                       float* sA, float2 (*sPart)[2], int rb, int nb) {
    int lane = threadIdx.x & 31;
    int gid  = lane >> 2, tig = lane & 3;
    const float* bb = sPar + l * 3 * 128;
    const float* gg = bb + 128;
    const float* tt = bb + 256;
    float s[4] = {0.f, 0.f, 0.f, 0.f}, s2[4] = {0.f, 0.f, 0.f, 0.f};
    #pragma unroll
    for (int mb = 0; mb < 2; ++mb)
        #pragma unroll
        for (int nt = 0; nt < 8; ++nt) {
            int col = nb * 64 + nt * 8 + 2 * tig;
            float2 b = *(const float2*)(bb + col);
            float t0 = fmaxf(acc[mb][nt][0] + b.x, 0.f);
            float t1 = fmaxf(acc[mb][nt][1] + b.y, 0.f);
            float t2 = fmaxf(acc[mb][nt][2] + b.x, 0.f);
            float t3 = fmaxf(acc[mb][nt][3] + b.y, 0.f);
            acc[mb][nt][0] = t0; acc[mb][nt][1] = t1;
            acc[mb][nt][2] = t2; acc[mb][nt][3] = t3;
            s[2*mb]    += t0 + t1; s2[2*mb]    = fmaf(t0, t0, fmaf(t1, t1, s2[2*mb]));
            s[2*mb+1]  += t2 + t3; s2[2*mb+1]  = fmaf(t2, t2, fmaf(t3, t3, s2[2*mb+1]));
        }
    #pragma unroll
    for (int m = 1; m <= 2; m <<= 1)
        #pragma unroll
        for (int k = 0; k < 4; ++k) {
            s[k]  += __shfl_xor_sync(0xffffffffu, s[k],  m);
            s2[k] += __shfl_xor_sync(0xffffffffu, s2[k], m);
        }
    int R[4] = {rb + gid, rb + gid + 8, rb + 16 + gid, rb + 24 + gid};
    if (tig == 0) {
        #pragma unroll
        for (int k = 0; k < 4; ++k) sPart[R[k]][nb] = make_float2(s[k], s2[k]);
    }
    __syncthreads();
    float mean[4], inv[4];
    #pragma unroll
    for (int k = 0; k < 4; ++k) {
        float2 p0 = sPart[R[k]][0], p1 = sPart[R[k]][1];
        float sm = p0.x + p1.x, sq = p0.y + p1.y;
        mean[k] = sm * 0.0078125f;
        inv[k]  = rsqrtf(fmaf(-mean[k], mean[k], sq * 0.0078125f) + 1e-5f);
    }
    #pragma unroll
    for (int mb = 0; mb < 2; ++mb)
        #pragma unroll
        for (int nt = 0; nt < 8; ++nt) {
            int col = nb * 64 + nt * 8 + 2 * tig;
            float2 g = *(const float2*)(gg + col);
            float2 t = *(const float2*)(tt + col);
            float2 va, vb;
            va.x = fmaf((acc[mb][nt][0] - mean[2*mb]) * inv[2*mb], g.x, t.x);
            va.y = fmaf((acc[mb][nt][1] - mean[2*mb]) * inv[2*mb], g.y, t.y);
            vb.x = fmaf((acc[mb][nt][2] - mean[2*mb+1]) * inv[2*mb+1], g.x, t.x);
            vb.y = fmaf((acc[mb][nt][3] - mean[2*mb+1]) * inv[2*mb+1], g.y, t.y);
            *(float2*)(sA + R[2*mb]   * SA_STR + col) = va;
            *(float2*)(sA + R[2*mb+1] * SA_STR + col) = vb;
        }
}

// final layer: acc + b4 -> sA (f32)
__device__ __forceinline__ void epi_final(float acc[2][8][4], const float* sPar,
                                          float* sA, int rb, int nb) {
    int lane = threadIdx.x & 31;
    int gid  = lane >> 2, tig = lane & 3;
    const float* b4 = sPar + 9 * 128;
    #pragma unroll
    for (int mb = 0; mb < 2; ++mb) {
        int r0 = rb + mb * 16 + gid;
        #pragma unroll
        for (int nt = 0; nt < 8; ++nt) {
            int col = nb * 64 + nt * 8 + 2 * tig;
            float2 b = *(const float2*)(b4 + col);
            float2 va, vb;
            va.x = acc[mb][nt][0] + b.x; va.y = acc[mb][nt][1] + b.y;
            vb.x = acc[mb][nt][2] + b.x; vb.y = acc[mb][nt][3] + b.y;
            *(float2*)(sA + r0 * SA_STR + col)       = va;
            *(float2*)(sA + (r0 + 8) * SA_STR + col) = vb;
        }
    }
}

// ---------------------------------------------------------------- edge kernel
__global__ void __launch_bounds__(THREADS)
edge_kernel(const float* __restrict__ x, const float* __restrict__ edge_attr,
            const int* __restrict__ edge_index,
            const float* __restrict__ W1, const float* __restrict__ W2,
            const float* __restrict__ W3, const float* __restrict__ W4,
            const float* __restrict__ b1, const float* __restrict__ g1, const float* __restrict__ t1,
            const float* __restrict__ b2, const float* __restrict__ g2, const float* __restrict__ t2,
            const float* __restrict__ b3, const float* __restrict__ g3, const float* __restrict__ t3,
            const float* __restrict__ b4,
            float* __restrict__ out_edge)
{
    extern __shared__ float smem[];
    float*    sA  = smem;                                 // [128][SA_STR] f32
    uint32_t* sBh = (uint32_t*)(smem + 128 * SA_STR);     // [64][SBW] bf16x2 hi
    uint32_t* sBl = sBh + 64 * SBW;                       // [64][SBW] bf16x2 lo
    __shared__ float  sPar[10 * 128];
    __shared__ float2 sPart[128][2];
    __shared__ int    sSrc[128], sDst[128];

    int tid = threadIdx.x;
    int w   = tid >> 5;
    int rb  = (w >> 1) * 32, nb = w & 1;
    size_t ebase = (size_t)blockIdx.x * 128;

    if (tid < 128) {
        sPar[0*128+tid] = b1[tid]; sPar[1*128+tid] = g1[tid]; sPar[2*128+tid] = t1[tid];
        sPar[3*128+tid] = b2[tid]; sPar[4*128+tid] = g2[tid]; sPar[5*128+tid] = t2[tid];
        sPar[6*128+tid] = b3[tid]; sPar[7*128+tid] = g3[tid]; sPar[8*128+tid] = t3[tid];
        sPar[9*128+tid] = b4[tid];
        sSrc[tid] = edge_index[ebase + tid];
        sDst[tid] = edge_index[(size_t)NE + ebase + tid];
    }
    __syncthreads();

    float acc[2][8][4];
    zero_acc(acc);

    // ---- layer 1: K = 384 in 3 chunks, accumulate in registers
    #pragma unroll 1
    for (int c = 0; c < 3; ++c) {
        #pragma unroll
        for (int i = tid; i < 4096; i += THREADS) {
            int r = i >> 5, j = i & 31;
            const float* src = (c == 0) ? edge_attr + (ebase + r) * H
                                        : x + (size_t)(c == 1 ? sSrc[r] : sDst[r]) * H;
            *(float4*)(sA + r * SA_STR + j * 4) = ((const float4*)src)[j];
        }
        fill_B(sBh, sBl, W1 + (size_t)c * 128 * H);
        __syncthreads();
        gemm128(sA, sBh, sBl, acc, rb, nb);
        __syncthreads();
    }

    // ---- layers 2..4
    const float* Ws[3] = {W2, W3, W4};
    #pragma unroll 1
    for (int l = 0; l < 3; ++l) {
        epi_ln(acc, sPar, l, sA, sPart, rb, nb);
        fill_B(sBh, sBl, Ws[l]);
        __syncthreads();
        zero_acc(acc);
        gemm128(sA, sBh, sBl, acc, rb, nb);
        __syncthreads();
    }

    // ---- final: + b4, residual write, atomic scatter of pre-residual
    epi_final(acc, sPar, sA, rb, nb);
    __syncthreads();

    #pragma unroll
    for (int i = tid; i < 4096; i += THREADS) {
        int r = i >> 5, j = i & 31;
        float4 val = *(float4*)(sA + r * SA_STR + j * 4);
        size_t e = ebase + r;
        float4 ea = ((const float4*)(edge_attr + e * H))[j];
        float4 o;
        o.x = ea.x + val.x; o.y = ea.y + val.y; o.z = ea.z + val.z; o.w = ea.w + val.w;
        ((float4*)(out_edge + e * H))[j] = o;
        atomicAdd((float4*)(g_agg + (size_t)sDst[r] * H + j * 4), val);
    }
}

// ---------------------------------------------------------------- node kernel
__global__ void __launch_bounds__(THREADS)
node_kernel(const float* __restrict__ x,
            const float* __restrict__ W1, const float* __restrict__ W2,
            const float* __restrict__ W3, const float* __restrict__ W4,
            const float* __restrict__ b1, const float* __restrict__ g1, const float* __restrict__ t1,
            const float* __restrict__ b2, const float* __restrict__ g2, const float* __restrict__ t2,
            const float* __restrict__ b3, const float* __restrict__ g3, const float* __restrict__ t3,
            const float* __restrict__ b4,
            float* __restrict__ out_node)
{
    extern __shared__ float smem[];
    float*    sA  = smem;
    uint32_t* sBh = (uint32_t*)(smem + 128 * SA_STR);
    uint32_t* sBl = sBh + 64 * SBW;
    __shared__ float  sPar[10 * 128];
    __shared__ float2 sPart[128][2];

    int tid = threadIdx.x;
    int w   = tid >> 5;
    int rb  = (w >> 1) * 32, nb = w & 1;
    size_t nbase = (size_t)blockIdx.x * 128;

    if (tid < 128) {
        sPar[0*128+tid] = b1[tid]; sPar[1*128+tid] = g1[tid]; sPar[2*128+tid] = t1[tid];
        sPar[3*128+tid] = b2[tid]; sPar[4*128+tid] = g2[tid]; sPar[5*128+tid] = t2[tid];
        sPar[6*128+tid] = b3[tid]; sPar[7*128+tid] = g3[tid]; sPar[8*128+tid] = t3[tid];
        sPar[9*128+tid] = b4[tid];
    }
    __syncthreads();

    float acc[2][8][4];
    zero_acc(acc);

    // ---- layer 1: K = 256 in 2 chunks ([x | agg])
    #pragma unroll 1
    for (int c = 0; c < 2; ++c) {
        const float* src0 = (c == 0) ? x : g_agg;
        #pragma unroll
        for (int i = tid; i < 4096; i += THREADS) {
            int r = i >> 5, j = i & 31;
            size_t node = nbase + r;
            float4 v = make_float4(0.f, 0.f, 0.f, 0.f);
            if (node < NN) v = ((const float4*)(src0 + node * H))[j];
            *(float4*)(sA + r * SA_STR + j * 4) = v;
        }
        fill_B(sBh, sBl, W1 + (size_t)c * 128 * H);
        __syncthreads();
        gemm128(sA, sBh, sBl, acc, rb, nb);
        __syncthreads();
    }

    const float* Ws[3] = {W2, W3, W4};
    #pragma unroll 1
    for (int l = 0; l < 3; ++l) {
        epi_ln(acc, sPar, l, sA, sPart, rb, nb);
        fill_B(sBh, sBl, Ws[l]);
        __syncthreads();
        zero_acc(acc);
        gemm128(sA, sBh, sBl, acc, rb, nb);
        __syncthreads();
    }

    epi_final(acc, sPar, sA, rb, nb);
    __syncthreads();

    #pragma unroll
    for (int i = tid; i < 4096; i += THREADS) {
        int r = i >> 5, j = i & 31;
        size_t node = nbase + r;
        if (node < NN) {
            float4 val = *(float4*)(sA + r * SA_STR + j * 4);
            float4 xv = ((const float4*)(x + node * H))[j];
            float4 o;
            o.x = xv.x + val.x; o.y = xv.y + val.y; o.z = xv.z + val.z; o.w = xv.w + val.w;
            ((float4*)(out_node + node * H))[j] = o;
        }
    }
}

// ---------------------------------------------------------------- launch
extern "C" void kernel_launch(void* const* d_in, const int* in_sizes, int n_in,
                              void* d_out, int out_size)
{
    const float* x          = (const float*)d_in[0];
    const float* edge_attr  = (const float*)d_in[1];
    const int*   edge_index = (const int*)d_in[2];

    const float* eW1 = (const float*)d_in[3];  const float* eb1 = (const float*)d_in[4];
    const float* eW2 = (const float*)d_in[5];  const float* eb2 = (const float*)d_in[6];
    const float* eW3 = (const float*)d_in[7];  const float* eb3 = (const float*)d_in[8];
    const float* eW4 = (const float*)d_in[9];  const float* eb4 = (const float*)d_in[10];
    const float* eg1 = (const float*)d_in[11]; const float* et1 = (const float*)d_in[12];
    const float* eg2 = (const float*)d_in[13]; const float* et2 = (const float*)d_in[14];
    const float* eg3 = (const float*)d_in[15]; const float* et3 = (const float*)d_in[16];

    const float* nW1 = (const float*)d_in[17]; const float* nb1 = (const float*)d_in[18];
    const float* nW2 = (const float*)d_in[19]; const float* nb2 = (const float*)d_in[20];
    const float* nW3 = (const float*)d_in[21]; const float* nb3 = (const float*)d_in[22];
    const float* nW4 = (const float*)d_in[23]; const float* nb4 = (const float*)d_in[24];
    const float* ng1 = (const float*)d_in[25]; const float* nt1 = (const float*)d_in[26];
    const float* ng2 = (const float*)d_in[27]; const float* nt2 = (const float*)d_in[28];
    const float* ng3 = (const float*)d_in[29]; const float* nt3 = (const float*)d_in[30];

    float* out_node = (float*)d_out;                   // [NN*H]
    float* out_edge = (float*)d_out + (size_t)NN * H;  // [NE*H]

    const int SMEM = (128 * SA_STR + 2 * 64 * SBW) * 4;  // 139264 B
    cudaFuncSetAttribute(edge_kernel, cudaFuncAttributeMaxDynamicSharedMemorySize, SMEM);
    cudaFuncSetAttribute(node_kernel, cudaFuncAttributeMaxDynamicSharedMemorySize, SMEM);

    zero_agg_kernel<<<(NN * H + 1023) / 1024, 1024>>>();

    edge_kernel<<<NE / 128, THREADS, SMEM>>>(
        x, edge_attr, edge_index,
        eW1, eW2, eW3, eW4,
        eb1, eg1, et1, eb2, eg2, et2, eb3, eg3, et3, eb4,
        out_edge);

    node_kernel<<<(NN + 127) / 128, THREADS, SMEM>>>(
        x,
        nW1, nW2, nW3, nW4,
        nb1, ng1, nt1, nb2, ng2, nt2, nb3, ng3, nt3, nb4,
        out_node);
}